// round 3
// baseline (speedup 1.0000x reference)
#include <cuda_runtime.h>
#include <cuda_bf16.h>
#include <math.h>

// Problem dims (fixed by reference)
#define B_   2
#define N_   4096
#define C_   768
#define H_   8
#define DH_  96
#define C3_  2304
#define M_   (B_ * N_)          // 8192 rows

// ---------------- device-global scratch (no allocations allowed) ----------------
__device__ float g_q[B_ * H_ * N_ * DH_];   // [B,H,N,Dh]
__device__ float g_k[B_ * H_ * N_ * DH_];
__device__ float g_v[B_ * H_ * N_ * DH_];
__device__ float g_att[B_ * N_ * C_];       // attention output [B,N,C]

// =====================================================================
// Kernel 1: QKV GEMM  qkv[8192,2304] = x[8192,768] @ w_qkv[768,2304]
// epilogue scatters into g_q/g_k/g_v with [B,H,N,Dh] layout.
// 64x64 tile, BK=16, 256 threads, 4x4 micro-tile.
// =====================================================================
__global__ __launch_bounds__(256) void qkv_gemm_kernel(
    const float* __restrict__ X, const float* __restrict__ W)
{
    __shared__ float As[64][16];
    __shared__ float Bs[16][64];

    const int tid = threadIdx.x;
    const int tx = tid & 15, ty = tid >> 4;
    const int m0 = blockIdx.y * 64;
    const int n0 = blockIdx.x * 64;

    float acc[4][4];
#pragma unroll
    for (int i = 0; i < 4; i++)
#pragma unroll
        for (int j = 0; j < 4; j++) acc[i][j] = 0.f;

    const int ra = tid >> 2, ca4 = tid & 3;     // A tile load coords
    const int rb = tid >> 4, cb4 = tid & 15;    // B tile load coords

    for (int k0 = 0; k0 < C_; k0 += 16) {
        float4 a4 = *(const float4*)(X + (size_t)(m0 + ra) * C_ + k0 + ca4 * 4);
        As[ra][ca4 * 4 + 0] = a4.x; As[ra][ca4 * 4 + 1] = a4.y;
        As[ra][ca4 * 4 + 2] = a4.z; As[ra][ca4 * 4 + 3] = a4.w;
        float4 b4 = *(const float4*)(W + (size_t)(k0 + rb) * C3_ + n0 + cb4 * 4);
        *(float4*)&Bs[rb][cb4 * 4] = b4;
        __syncthreads();

#pragma unroll
        for (int kk = 0; kk < 16; kk++) {
            float a[4];
            float4 bv = *(float4*)&Bs[kk][tx * 4];
            float b[4] = {bv.x, bv.y, bv.z, bv.w};
#pragma unroll
            for (int i = 0; i < 4; i++) a[i] = As[ty * 4 + i][kk];
#pragma unroll
            for (int i = 0; i < 4; i++)
#pragma unroll
                for (int j = 0; j < 4; j++) acc[i][j] += a[i] * b[j];
        }
        __syncthreads();
    }

    // scatter epilogue: column jg -> s (q/k/v), head h, d
    const int b = m0 >> 12;                 // batch index (4096 % 64 == 0)
    const int s = n0 / C_;                  // constant per block (768 % 64 == 0)
    float* dstbase = (s == 0) ? g_q : ((s == 1) ? g_k : g_v);
#pragma unroll
    for (int i = 0; i < 4; i++) {
        const int m = m0 + ty * 4 + i;
        const int n = m & (N_ - 1);
#pragma unroll
        for (int j = 0; j < 4; j++) {
            const int jg = n0 + tx * 4 + j;
            const int r  = jg - s * C_;
            const int h  = r / DH_;
            const int d  = r - h * DH_;
            dstbase[(((size_t)(b * H_ + h)) * N_ + n) * DH_ + d] = acc[i][j];
        }
    }
}

// =====================================================================
// Kernel 2: flash attention, fp32.
// grid: (N/64, B*H). block 256 = 16x16. BQ=BKV=64.
// Thread (ty,tx): S rows r=ty+16i (i<4), S cols c=tx+16j (j<4),
//                 O rows same, O cols tx*6..tx*6+5.
// Online softmax per-row state kept in registers (shuffle over 16 lanes).
// =====================================================================
#define ATT_SMEM_FLOATS (64*97 + 64*97 + 64*96 + 64*80)

__global__ __launch_bounds__(256) void attn_kernel()
{
    extern __shared__ float sm[];
    float* Qs = sm;               // [64][97]
    float* Ks = Qs + 64 * 97;     // [64][97]
    float* Vs = Ks + 64 * 97;     // [64][96]
    float* Ps = Vs + 64 * 96;     // [64][80]

    const int bh  = blockIdx.y;           // 0..15
    const int q0  = blockIdx.x * 64;
    const int tid = threadIdx.x;
    const int tx  = tid & 15, ty = tid >> 4;

    const float* qb = g_q + (size_t)bh * N_ * DH_;
    const float* kb = g_k + (size_t)bh * N_ * DH_;
    const float* vb = g_v + (size_t)bh * N_ * DH_;

    // load Q tile [64][96] -> Qs padded 97
    for (int e = tid; e < 64 * 24; e += 256) {
        int r = e / 24, c4 = e % 24;
        float4 v4 = *(const float4*)(qb + (size_t)(q0 + r) * DH_ + c4 * 4);
        float* dst = Qs + r * 97 + c4 * 4;
        dst[0] = v4.x; dst[1] = v4.y; dst[2] = v4.z; dst[3] = v4.w;
    }

    float m_i[4], l_i[4], Oacc[4][6];
#pragma unroll
    for (int i = 0; i < 4; i++) {
        m_i[i] = -1e30f; l_i[i] = 0.f;
#pragma unroll
        for (int c = 0; c < 6; c++) Oacc[i][c] = 0.f;
    }
    const float scale = rsqrtf((float)DH_);

    for (int t0 = 0; t0 < N_; t0 += 64) {
        __syncthreads();   // previous Ps/Vs reads done; also covers initial Qs fill
        for (int e = tid; e < 64 * 24; e += 256) {
            int r = e / 24, c4 = e % 24;
            float4 k4 = *(const float4*)(kb + (size_t)(t0 + r) * DH_ + c4 * 4);
            float* kd = Ks + r * 97 + c4 * 4;
            kd[0] = k4.x; kd[1] = k4.y; kd[2] = k4.z; kd[3] = k4.w;
            float4 v4 = *(const float4*)(vb + (size_t)(t0 + r) * DH_ + c4 * 4);
            *(float4*)(Vs + r * 96 + c4 * 4) = v4;
        }
        __syncthreads();

        // S = Q @ K^T (register 4x4)
        float s[4][4];
#pragma unroll
        for (int i = 0; i < 4; i++)
#pragma unroll
            for (int j = 0; j < 4; j++) s[i][j] = 0.f;

#pragma unroll 2
        for (int d = 0; d < DH_; d++) {
            float qv[4], kv[4];
#pragma unroll
            for (int i = 0; i < 4; i++) qv[i] = Qs[(ty + 16 * i) * 97 + d];
#pragma unroll
            for (int j = 0; j < 4; j++) kv[j] = Ks[(tx + 16 * j) * 97 + d];
#pragma unroll
            for (int i = 0; i < 4; i++)
#pragma unroll
                for (int j = 0; j < 4; j++) s[i][j] += qv[i] * kv[j];
        }

        // online softmax per row group (16 lanes share a row set)
        float alpha[4];
#pragma unroll
        for (int i = 0; i < 4; i++) {
            float mt = -1e30f;
#pragma unroll
            for (int j = 0; j < 4; j++) { s[i][j] *= scale; mt = fmaxf(mt, s[i][j]); }
#pragma unroll
            for (int off = 8; off >= 1; off >>= 1)
                mt = fmaxf(mt, __shfl_xor_sync(0xffffffffu, mt, off));
            float mnew = fmaxf(m_i[i], mt);
            alpha[i] = __expf(m_i[i] - mnew);
            float ls = 0.f;
#pragma unroll
            for (int j = 0; j < 4; j++) { s[i][j] = __expf(s[i][j] - mnew); ls += s[i][j]; }
#pragma unroll
            for (int off = 8; off >= 1; off >>= 1)
                ls += __shfl_xor_sync(0xffffffffu, ls, off);
            l_i[i] = l_i[i] * alpha[i] + ls;
            m_i[i] = mnew;
#pragma unroll
            for (int j = 0; j < 4; j++)
                Ps[(ty + 16 * i) * 80 + tx + 16 * j] = s[i][j];
        }
        __syncthreads();

        // O = O*alpha + P @ V
#pragma unroll
        for (int i = 0; i < 4; i++)
#pragma unroll
            for (int c = 0; c < 6; c++) Oacc[i][c] *= alpha[i];

#pragma unroll 2
        for (int k = 0; k < 64; k++) {
            float pv[4], vv[6];
#pragma unroll
            for (int i = 0; i < 4; i++) pv[i] = Ps[(ty + 16 * i) * 80 + k];
#pragma unroll
            for (int c = 0; c < 6; c++) vv[c] = Vs[k * 96 + tx * 6 + c];
#pragma unroll
            for (int i = 0; i < 4; i++)
#pragma unroll
                for (int c = 0; c < 6; c++) Oacc[i][c] += pv[i] * vv[c];
        }
    }

    // epilogue: normalize and write to [B,N,C] (transpose-merge of heads)
    const int b = bh >> 3, h = bh & 7;
#pragma unroll
    for (int i = 0; i < 4; i++) {
        const float inv = 1.f / l_i[i];
        const int r = q0 + ty + 16 * i;
        float* dst = g_att + ((size_t)(b * N_ + r)) * C_ + h * DH_ + tx * 6;
#pragma unroll
        for (int c = 0; c < 6; c++) dst[c] = Oacc[i][c] * inv;
    }
}

// =====================================================================
// Kernel 3: out projection  out[8192,768] = att[8192,768] @ w_proj + b_proj
// =====================================================================
__global__ __launch_bounds__(256) void proj_gemm_kernel(
    const float* __restrict__ W, const float* __restrict__ bias,
    float* __restrict__ out)
{
    __shared__ float As[64][16];
    __shared__ float Bs[16][64];

    const int tid = threadIdx.x;
    const int tx = tid & 15, ty = tid >> 4;
    const int m0 = blockIdx.y * 64;
    const int n0 = blockIdx.x * 64;

    float acc[4][4];
#pragma unroll
    for (int i = 0; i < 4; i++)
#pragma unroll
        for (int j = 0; j < 4; j++) acc[i][j] = 0.f;

    const int ra = tid >> 2, ca4 = tid & 3;
    const int rb = tid >> 4, cb4 = tid & 15;

    for (int k0 = 0; k0 < C_; k0 += 16) {
        float4 a4 = *(const float4*)(g_att + (size_t)(m0 + ra) * C_ + k0 + ca4 * 4);
        As[ra][ca4 * 4 + 0] = a4.x; As[ra][ca4 * 4 + 1] = a4.y;
        As[ra][ca4 * 4 + 2] = a4.z; As[ra][ca4 * 4 + 3] = a4.w;
        float4 b4 = *(const float4*)(W + (size_t)(k0 + rb) * C_ + n0 + cb4 * 4);
        *(float4*)&Bs[rb][cb4 * 4] = b4;
        __syncthreads();

#pragma unroll
        for (int kk = 0; kk < 16; kk++) {
            float a[4];
            float4 bv = *(float4*)&Bs[kk][tx * 4];
            float b[4] = {bv.x, bv.y, bv.z, bv.w};
#pragma unroll
            for (int i = 0; i < 4; i++) a[i] = As[ty * 4 + i][kk];
#pragma unroll
            for (int i = 0; i < 4; i++)
#pragma unroll
                for (int j = 0; j < 4; j++) acc[i][j] += a[i] * b[j];
        }
        __syncthreads();
    }

#pragma unroll
    for (int i = 0; i < 4; i++) {
        const int m = m0 + ty * 4 + i;
#pragma unroll
        for (int j = 0; j < 4; j++) {
            const int jg = n0 + tx * 4 + j;
            out[(size_t)m * C_ + jg] = acc[i][j] + bias[jg];
        }
    }
}

// =====================================================================
extern "C" void kernel_launch(void* const* d_in, const int* in_sizes, int n_in,
                              void* d_out, int out_size)
{
    const float* x     = (const float*)d_in[0];
    const float* wqkv  = (const float*)d_in[1];
    const float* wproj = (const float*)d_in[2];
    const float* bproj = (const float*)d_in[3];
    float* out = (float*)d_out;

    (void)in_sizes; (void)n_in; (void)out_size;

    // 1. QKV projection + scatter
    {
        dim3 grid(C3_ / 64, M_ / 64);   // (36, 128)
        qkv_gemm_kernel<<<grid, 256>>>(x, wqkv);
    }

    // 2. flash attention
    {
        const int smem_bytes = ATT_SMEM_FLOATS * (int)sizeof(float); // 94720
        cudaFuncSetAttribute(attn_kernel,
                             cudaFuncAttributeMaxDynamicSharedMemorySize, smem_bytes);
        dim3 grid(N_ / 64, B_ * H_);    // (64, 16)
        attn_kernel<<<grid, 256, smem_bytes>>>();
    }

    // 3. output projection + bias
    {
        dim3 grid(C_ / 64, M_ / 64);    // (12, 128)
        proj_gemm_kernel<<<grid, 256>>>(wproj, bproj, out);
    }
}

// round 4
// speedup vs baseline: 1.8905x; 1.8905x over previous
#include <cuda_runtime.h>
#include <cuda_bf16.h>
#include <math.h>
#include <stdint.h>

// Problem dims (fixed by reference)
#define B_   2
#define N_   4096
#define C_   768
#define H_   8
#define DH_  96
#define C3_  2304
#define M_   (B_ * N_)          // 8192 rows

#define QK_SCALE 0.10206207261596577f   // 96^-0.5

// ---------------- device-global scratch (no allocations allowed) ----------------
// Split-precision bf16 Q/K/V, [B,H,N,Dh]; Q pre-scaled by QK_SCALE.
__device__ __align__(16) __nv_bfloat16 g_qh[B_ * H_ * N_ * DH_];
__device__ __align__(16) __nv_bfloat16 g_ql[B_ * H_ * N_ * DH_];
__device__ __align__(16) __nv_bfloat16 g_kh[B_ * H_ * N_ * DH_];
__device__ __align__(16) __nv_bfloat16 g_kl[B_ * H_ * N_ * DH_];
__device__ __align__(16) __nv_bfloat16 g_vh[B_ * H_ * N_ * DH_];
__device__ __align__(16) __nv_bfloat16 g_vl[B_ * H_ * N_ * DH_];
__device__ float g_att[B_ * N_ * C_];       // attention output [B,N,C]

// ---------------- mma / ldmatrix helpers ----------------
#define LDSM4(d, a) asm volatile( \
    "ldmatrix.sync.aligned.m8n8.x4.shared.b16 {%0,%1,%2,%3}, [%4];" \
    : "=r"((d)[0]), "=r"((d)[1]), "=r"((d)[2]), "=r"((d)[3]) : "r"(a))
#define LDSM2(d, a) asm volatile( \
    "ldmatrix.sync.aligned.m8n8.x2.shared.b16 {%0,%1}, [%2];" \
    : "=r"((d)[0]), "=r"((d)[1]) : "r"(a))
#define LDSM2T(d, a) asm volatile( \
    "ldmatrix.sync.aligned.m8n8.x2.trans.shared.b16 {%0,%1}, [%2];" \
    : "=r"((d)[0]), "=r"((d)[1]) : "r"(a))
#define MMA16816(c, a, b) asm volatile( \
    "mma.sync.aligned.m16n8k16.row.col.f32.bf16.bf16.f32 " \
    "{%0,%1,%2,%3}, {%4,%5,%6,%7}, {%8,%9}, {%0,%1,%2,%3};" \
    : "+f"((c)[0]), "+f"((c)[1]), "+f"((c)[2]), "+f"((c)[3]) \
    : "r"((a)[0]), "r"((a)[1]), "r"((a)[2]), "r"((a)[3]), "r"((b)[0]), "r"((b)[1]))

__device__ __forceinline__ uint32_t packpair(float lo, float hi) {
    __nv_bfloat162 t = __floats2bfloat162_rn(lo, hi);   // .x = lo (low 16), .y = hi
    return *(uint32_t*)&t;
}
__device__ __forceinline__ float bf_res(float x) {
    return x - __bfloat162float(__float2bfloat16(x));
}

// =====================================================================
// Kernel 1: QKV GEMM  qkv[8192,2304] = x[8192,768] @ w_qkv[768,2304]
// epilogue splits each value into bf16 hi/lo (Q pre-scaled) and scatters
// into [B,H,N,Dh] layout.
// =====================================================================
__global__ __launch_bounds__(256) void qkv_gemm_kernel(
    const float* __restrict__ X, const float* __restrict__ W)
{
    __shared__ float As[64][16];
    __shared__ float Bs[16][64];

    const int tid = threadIdx.x;
    const int tx = tid & 15, ty = tid >> 4;
    const int m0 = blockIdx.y * 64;
    const int n0 = blockIdx.x * 64;

    float acc[4][4];
#pragma unroll
    for (int i = 0; i < 4; i++)
#pragma unroll
        for (int j = 0; j < 4; j++) acc[i][j] = 0.f;

    const int ra = tid >> 2, ca4 = tid & 3;
    const int rb = tid >> 4, cb4 = tid & 15;

    for (int k0 = 0; k0 < C_; k0 += 16) {
        float4 a4 = *(const float4*)(X + (size_t)(m0 + ra) * C_ + k0 + ca4 * 4);
        As[ra][ca4 * 4 + 0] = a4.x; As[ra][ca4 * 4 + 1] = a4.y;
        As[ra][ca4 * 4 + 2] = a4.z; As[ra][ca4 * 4 + 3] = a4.w;
        float4 b4 = *(const float4*)(W + (size_t)(k0 + rb) * C3_ + n0 + cb4 * 4);
        *(float4*)&Bs[rb][cb4 * 4] = b4;
        __syncthreads();

#pragma unroll
        for (int kk = 0; kk < 16; kk++) {
            float a[4];
            float4 bv = *(float4*)&Bs[kk][tx * 4];
            float b[4] = {bv.x, bv.y, bv.z, bv.w};
#pragma unroll
            for (int i = 0; i < 4; i++) a[i] = As[ty * 4 + i][kk];
#pragma unroll
            for (int i = 0; i < 4; i++)
#pragma unroll
                for (int j = 0; j < 4; j++) acc[i][j] += a[i] * b[j];
        }
        __syncthreads();
    }

    const int b = m0 >> 12;                 // batch index
    const int s = n0 / C_;                  // 0=q, 1=k, 2=v (768 % 64 == 0)
#pragma unroll
    for (int i = 0; i < 4; i++) {
        const int m = m0 + ty * 4 + i;
        const int n = m & (N_ - 1);
#pragma unroll
        for (int j = 0; j < 4; j++) {
            const int jg = n0 + tx * 4 + j;
            const int r  = jg - s * C_;
            const int h  = r / DH_;
            const int d  = r - h * DH_;
            const size_t off = (((size_t)(b * H_ + h)) * N_ + n) * DH_ + d;
            float v = acc[i][j];
            if (s == 0) v *= QK_SCALE;
            __nv_bfloat16 hi = __float2bfloat16(v);
            __nv_bfloat16 lo = __float2bfloat16(v - __bfloat162float(hi));
            if (s == 0)      { g_qh[off] = hi; g_ql[off] = lo; }
            else if (s == 1) { g_kh[off] = hi; g_kl[off] = lo; }
            else             { g_vh[off] = hi; g_vl[off] = lo; }
        }
    }
}

// =====================================================================
// Kernel 2: flash attention on tensor cores (mma.sync bf16, hi/lo split).
// grid (N/64, B*H), block 128 = 4 warps. Warp w owns q-rows [w*16, w*16+16).
// Per 64-key tile: S = Q K^T via 6(k) x 8(n) x 3(split) MMAs, register
// online softmax, P repacked in regs to A-fragments, O += P V via
// 4(k) x 12(n) x 3 MMAs.
// =====================================================================
#define RS   104                 // smem row stride, bf16 elems
#define RSB  (RS * 2)            // bytes (208 = 13 * 16)
#define SEG  (64 * RS)           // elems per tile array
#define ATT_SMEM_BYTES (6 * SEG * 2)   // 79872

__global__ __launch_bounds__(128) void attn_kernel()
{
    extern __shared__ __align__(16) char smem[];
    uint4* sQh4 = (uint4*)smem;                       // 64 x 13 uint4
    uint4* sQl4 = (uint4*)(smem + 1 * SEG * 2);
    uint4* sKh4 = (uint4*)(smem + 2 * SEG * 2);
    uint4* sKl4 = (uint4*)(smem + 3 * SEG * 2);
    uint4* sVh4 = (uint4*)(smem + 4 * SEG * 2);
    uint4* sVl4 = (uint4*)(smem + 5 * SEG * 2);

    const int tid  = threadIdx.x;
    const int lane = tid & 31;
    const int w    = tid >> 5;
    const int bh   = blockIdx.y;
    const int q0   = blockIdx.x * 64;

    const uint32_t sb   = (uint32_t)__cvta_generic_to_shared(smem);
    const uint32_t Qh_b = sb;
    const uint32_t Ql_b = sb + 1 * SEG * 2;
    const uint32_t Kh_b = sb + 2 * SEG * 2;
    const uint32_t Kl_b = sb + 3 * SEG * 2;
    const uint32_t Vh_b = sb + 4 * SEG * 2;
    const uint32_t Vl_b = sb + 5 * SEG * 2;

    // ---- load Q tile (rows q0..q0+63), 12 uint4 per row ----
    const uint4* q4h = (const uint4*)g_qh;
    const uint4* q4l = (const uint4*)g_ql;
    const size_t qrow0 = (size_t)bh * N_ + q0;
    for (int e = tid; e < 64 * 12; e += 128) {
        const int r = e / 12, c = e % 12;
        sQh4[r * 13 + c] = q4h[(qrow0 + r) * 12 + c];
        sQl4[r * 13 + c] = q4l[(qrow0 + r) * 12 + c];
    }

    // per-lane fragment address offsets
    const int mloc = w * 16;
    const uint32_t qa_off = (uint32_t)((mloc + (lane & 7) + 8 * ((lane >> 3) & 1)) * RSB
                                       + (lane >> 4) * 16);
    const int l16 = lane & 15;
    const uint32_t kb_off = (uint32_t)((l16 & 7) * RSB + ((l16 >> 3) & 1) * 16);
    const uint32_t vb_off = (uint32_t)(((l16 & 7) + 8 * ((l16 >> 3) & 1)) * RSB);

    float oc[12][4];
#pragma unroll
    for (int nt = 0; nt < 12; nt++)
#pragma unroll
        for (int i = 0; i < 4; i++) oc[nt][i] = 0.f;
    float mprev[2] = {-1e30f, -1e30f};
    float lsum[2]  = {0.f, 0.f};

    const uint4* k4h = (const uint4*)g_kh;
    const uint4* k4l = (const uint4*)g_kl;
    const uint4* v4h = (const uint4*)g_vh;
    const uint4* v4l = (const uint4*)g_vl;

    for (int t0 = 0; t0 < N_; t0 += 64) {
        __syncthreads();   // prior-iter Vs reads done (also orders Q stores)
        const size_t krow0 = (size_t)bh * N_ + t0;
        for (int e = tid; e < 64 * 12; e += 128) {
            const int r = e / 12, c = e % 12;
            const size_t gi = (krow0 + r) * 12 + c;
            const int si = r * 13 + c;
            sKh4[si] = k4h[gi];
            sKl4[si] = k4l[gi];
            sVh4[si] = v4h[gi];
            sVl4[si] = v4l[gi];
        }
        __syncthreads();

        // ---- S = Q K^T  (scale pre-folded into Q) ----
        float sc[8][4];
#pragma unroll
        for (int nt = 0; nt < 8; nt++)
#pragma unroll
            for (int i = 0; i < 4; i++) sc[nt][i] = 0.f;

#pragma unroll
        for (int kc = 0; kc < 6; kc++) {
            uint32_t qh[4], ql[4];
            LDSM4(qh, Qh_b + qa_off + kc * 32);
            LDSM4(ql, Ql_b + qa_off + kc * 32);
#pragma unroll
            for (int nt = 0; nt < 8; nt++) {
                uint32_t kh[2], kl[2];
                const uint32_t off = kb_off + (uint32_t)(nt * 8 * RSB) + kc * 32;
                LDSM2(kh, Kh_b + off);
                LDSM2(kl, Kl_b + off);
                MMA16816(sc[nt], qh, kh);
                MMA16816(sc[nt], qh, kl);
                MMA16816(sc[nt], ql, kh);
            }
        }

        // ---- online softmax (rows rh=0: lane/4, rh=1: lane/4+8) ----
        float alpha[2];
#pragma unroll
        for (int rh = 0; rh < 2; rh++) {
            float mt = -1e30f;
#pragma unroll
            for (int nt = 0; nt < 8; nt++)
                mt = fmaxf(mt, fmaxf(sc[nt][2 * rh], sc[nt][2 * rh + 1]));
            mt = fmaxf(mt, __shfl_xor_sync(0xffffffffu, mt, 1));
            mt = fmaxf(mt, __shfl_xor_sync(0xffffffffu, mt, 2));
            const float mnew = fmaxf(mprev[rh], mt);
            alpha[rh] = __expf(mprev[rh] - mnew);
            float ls = 0.f;
#pragma unroll
            for (int nt = 0; nt < 8; nt++) {
                const float e0 = __expf(sc[nt][2 * rh]     - mnew);
                const float e1 = __expf(sc[nt][2 * rh + 1] - mnew);
                sc[nt][2 * rh] = e0; sc[nt][2 * rh + 1] = e1;
                ls += e0 + e1;
            }
            ls += __shfl_xor_sync(0xffffffffu, ls, 1);
            ls += __shfl_xor_sync(0xffffffffu, ls, 2);
            lsum[rh] = lsum[rh] * alpha[rh] + ls;
            mprev[rh] = mnew;
        }
#pragma unroll
        for (int nt = 0; nt < 12; nt++) {
            oc[nt][0] *= alpha[0]; oc[nt][1] *= alpha[0];
            oc[nt][2] *= alpha[1]; oc[nt][3] *= alpha[1];
        }

        // ---- O += P V ----
#pragma unroll
        for (int kc = 0; kc < 4; kc++) {
            const int ta = 2 * kc, tb = 2 * kc + 1;
            uint32_t ph[4], pl[4];
            ph[0] = packpair(sc[ta][0], sc[ta][1]);
            ph[1] = packpair(sc[ta][2], sc[ta][3]);
            ph[2] = packpair(sc[tb][0], sc[tb][1]);
            ph[3] = packpair(sc[tb][2], sc[tb][3]);
            pl[0] = packpair(bf_res(sc[ta][0]), bf_res(sc[ta][1]));
            pl[1] = packpair(bf_res(sc[ta][2]), bf_res(sc[ta][3]));
            pl[2] = packpair(bf_res(sc[tb][0]), bf_res(sc[tb][1]));
            pl[3] = packpair(bf_res(sc[tb][2]), bf_res(sc[tb][3]));
#pragma unroll
            for (int nt = 0; nt < 12; nt++) {
                uint32_t vh[2], vl[2];
                const uint32_t off = vb_off + (uint32_t)(kc * 16 * RSB) + nt * 16;
                LDSM2T(vh, Vh_b + off);
                LDSM2T(vl, Vl_b + off);
                MMA16816(oc[nt], ph, vh);
                MMA16816(oc[nt], ph, vl);
                MMA16816(oc[nt], pl, vh);
            }
        }
    }

    // ---- epilogue: normalize, write [B,N,C] ----
    const int b = bh >> 3, h = bh & 7;
    const int r0 = q0 + mloc + (lane >> 2);
    const float inv0 = 1.f / lsum[0];
    const float inv1 = 1.f / lsum[1];
    float* o0 = g_att + ((size_t)(b * N_ + r0)) * C_ + h * DH_ + 2 * (lane & 3);
    float* o1 = o0 + (size_t)8 * C_;
#pragma unroll
    for (int nt = 0; nt < 12; nt++) {
        float2 u0 = make_float2(oc[nt][0] * inv0, oc[nt][1] * inv0);
        float2 u1 = make_float2(oc[nt][2] * inv1, oc[nt][3] * inv1);
        *(float2*)(o0 + nt * 8) = u0;
        *(float2*)(o1 + nt * 8) = u1;
    }
}

// =====================================================================
// Kernel 3: out projection  out[8192,768] = att[8192,768] @ w_proj + b_proj
// =====================================================================
__global__ __launch_bounds__(256) void proj_gemm_kernel(
    const float* __restrict__ W, const float* __restrict__ bias,
    float* __restrict__ out)
{
    __shared__ float As[64][16];
    __shared__ float Bs[16][64];

    const int tid = threadIdx.x;
    const int tx = tid & 15, ty = tid >> 4;
    const int m0 = blockIdx.y * 64;
    const int n0 = blockIdx.x * 64;

    float acc[4][4];
#pragma unroll
    for (int i = 0; i < 4; i++)
#pragma unroll
        for (int j = 0; j < 4; j++) acc[i][j] = 0.f;

    const int ra = tid >> 2, ca4 = tid & 3;
    const int rb = tid >> 4, cb4 = tid & 15;

    for (int k0 = 0; k0 < C_; k0 += 16) {
        float4 a4 = *(const float4*)(g_att + (size_t)(m0 + ra) * C_ + k0 + ca4 * 4);
        As[ra][ca4 * 4 + 0] = a4.x; As[ra][ca4 * 4 + 1] = a4.y;
        As[ra][ca4 * 4 + 2] = a4.z; As[ra][ca4 * 4 + 3] = a4.w;
        float4 b4 = *(const float4*)(W + (size_t)(k0 + rb) * C_ + n0 + cb4 * 4);
        *(float4*)&Bs[rb][cb4 * 4] = b4;
        __syncthreads();

#pragma unroll
        for (int kk = 0; kk < 16; kk++) {
            float a[4];
            float4 bv = *(float4*)&Bs[kk][tx * 4];
            float b[4] = {bv.x, bv.y, bv.z, bv.w};
#pragma unroll
            for (int i = 0; i < 4; i++) a[i] = As[ty * 4 + i][kk];
#pragma unroll
            for (int i = 0; i < 4; i++)
#pragma unroll
                for (int j = 0; j < 4; j++) acc[i][j] += a[i] * b[j];
        }
        __syncthreads();
    }

#pragma unroll
    for (int i = 0; i < 4; i++) {
        const int m = m0 + ty * 4 + i;
#pragma unroll
        for (int j = 0; j < 4; j++) {
            const int jg = n0 + tx * 4 + j;
            out[(size_t)m * C_ + jg] = acc[i][j] + bias[jg];
        }
    }
}

// =====================================================================
extern "C" void kernel_launch(void* const* d_in, const int* in_sizes, int n_in,
                              void* d_out, int out_size)
{
    const float* x     = (const float*)d_in[0];
    const float* wqkv  = (const float*)d_in[1];
    const float* wproj = (const float*)d_in[2];
    const float* bproj = (const float*)d_in[3];
    float* out = (float*)d_out;

    (void)in_sizes; (void)n_in; (void)out_size;

    // 1. QKV projection + bf16 hi/lo split scatter
    {
        dim3 grid(C3_ / 64, M_ / 64);   // (36, 128)
        qkv_gemm_kernel<<<grid, 256>>>(x, wqkv);
    }

    // 2. flash attention (tensor cores)
    {
        cudaFuncSetAttribute(attn_kernel,
                             cudaFuncAttributeMaxDynamicSharedMemorySize, ATT_SMEM_BYTES);
        dim3 grid(N_ / 64, B_ * H_);    // (64, 16)
        attn_kernel<<<grid, 128, ATT_SMEM_BYTES>>>();
    }

    // 3. output projection + bias
    {
        dim3 grid(C_ / 64, M_ / 64);    // (12, 128)
        proj_gemm_kernel<<<grid, 256>>>(wproj, bproj, out);
    }
}

// round 5
// speedup vs baseline: 2.4800x; 1.3118x over previous
#include <cuda_runtime.h>
#include <cuda_bf16.h>
#include <math.h>
#include <stdint.h>

// Problem dims (fixed by reference)
#define B_   2
#define N_   4096
#define C_   768
#define H_   8
#define DH_  96
#define C3_  2304
#define M_   (B_ * N_)          // 8192 rows

#define QK_SCALE 0.10206207261596577f   // 96^-0.5

// ---------------- device-global scratch ----------------
__device__ __align__(16) __nv_bfloat16 g_xh[M_ * C_];
__device__ __align__(16) __nv_bfloat16 g_xl[M_ * C_];
__device__ __align__(16) __nv_bfloat16 g_wqh[C_ * C3_];
__device__ __align__(16) __nv_bfloat16 g_wql[C_ * C3_];
__device__ __align__(16) __nv_bfloat16 g_wph[C_ * C_];
__device__ __align__(16) __nv_bfloat16 g_wpl[C_ * C_];
// Split-precision bf16 Q/K/V, [B,H,N,Dh]; Q pre-scaled by QK_SCALE.
__device__ __align__(16) __nv_bfloat16 g_qh[B_ * H_ * N_ * DH_];
__device__ __align__(16) __nv_bfloat16 g_ql[B_ * H_ * N_ * DH_];
__device__ __align__(16) __nv_bfloat16 g_kh[B_ * H_ * N_ * DH_];
__device__ __align__(16) __nv_bfloat16 g_kl[B_ * H_ * N_ * DH_];
__device__ __align__(16) __nv_bfloat16 g_vh[B_ * H_ * N_ * DH_];
__device__ __align__(16) __nv_bfloat16 g_vl[B_ * H_ * N_ * DH_];
// attention output, split bf16 [B,N,C]
__device__ __align__(16) __nv_bfloat16 g_ath[B_ * N_ * C_];
__device__ __align__(16) __nv_bfloat16 g_atl[B_ * N_ * C_];

// ---------------- mma / ldmatrix helpers ----------------
#define LDSM4(d, a) asm volatile( \
    "ldmatrix.sync.aligned.m8n8.x4.shared.b16 {%0,%1,%2,%3}, [%4];" \
    : "=r"((d)[0]), "=r"((d)[1]), "=r"((d)[2]), "=r"((d)[3]) : "r"(a))
#define LDSM2(d, a) asm volatile( \
    "ldmatrix.sync.aligned.m8n8.x2.shared.b16 {%0,%1}, [%2];" \
    : "=r"((d)[0]), "=r"((d)[1]) : "r"(a))
#define LDSM2T(d, a) asm volatile( \
    "ldmatrix.sync.aligned.m8n8.x2.trans.shared.b16 {%0,%1}, [%2];" \
    : "=r"((d)[0]), "=r"((d)[1]) : "r"(a))
#define MMA16816(c, a, b) asm volatile( \
    "mma.sync.aligned.m16n8k16.row.col.f32.bf16.bf16.f32 " \
    "{%0,%1,%2,%3}, {%4,%5,%6,%7}, {%8,%9}, {%0,%1,%2,%3};" \
    : "+f"((c)[0]), "+f"((c)[1]), "+f"((c)[2]), "+f"((c)[3]) \
    : "r"((a)[0]), "r"((a)[1]), "r"((a)[2]), "r"((a)[3]), "r"((b)[0]), "r"((b)[1]))

__device__ __forceinline__ uint32_t packpair(float lo, float hi) {
    __nv_bfloat162 t = __floats2bfloat162_rn(lo, hi);
    return *(uint32_t*)&t;
}
__device__ __forceinline__ float bf_res(float x) {
    return x - __bfloat162float(__float2bfloat16(x));
}
__device__ __forceinline__ void split2(float v0, float v1,
                                       __nv_bfloat162& h2, __nv_bfloat162& l2) {
    __nv_bfloat16 h0 = __float2bfloat16(v0);
    __nv_bfloat16 h1 = __float2bfloat16(v1);
    __nv_bfloat16 l0 = __float2bfloat16(v0 - __bfloat162float(h0));
    __nv_bfloat16 l1 = __float2bfloat16(v1 - __bfloat162float(h1));
    h2 = __nv_bfloat162(h0, h1);
    l2 = __nv_bfloat162(l0, l1);
}

// =====================================================================
// split kernel: fp32 -> bf16 hi/lo (vectorized float4)
// =====================================================================
__global__ void split_kernel(const float* __restrict__ src,
                             __nv_bfloat16* __restrict__ h,
                             __nv_bfloat16* __restrict__ l, int n4)
{
    int i = blockIdx.x * blockDim.x + threadIdx.x;
    if (i >= n4) return;
    float4 v = ((const float4*)src)[i];
    __nv_bfloat162 h0, l0, h1, l1;
    split2(v.x, v.y, h0, l0);
    split2(v.z, v.w, h1, l1);
    ((__nv_bfloat162*)h)[2 * i]     = h0;
    ((__nv_bfloat162*)h)[2 * i + 1] = h1;
    ((__nv_bfloat162*)l)[2 * i]     = l0;
    ((__nv_bfloat162*)l)[2 * i + 1] = l1;
}

// =====================================================================
// MMA GEMM body (128x128 tile, BK=32, 8 warps, warp tile 64x32).
// A[M][K] row-major split (ah,al), Bmat[K][N] row-major split (bh,bl).
// acc = ah*bh + ah*bl + al*bh.
// =====================================================================
#define AS_  40                 // A smem row stride (bf16)
#define BS_  136                // B smem row stride (bf16)

struct GemmFrag { float acc[4][4][4]; };

template<int LDA_U4, int LDB_U4>
__device__ __forceinline__ void mma_gemm_tile(
    const uint4* __restrict__ a4h, const uint4* __restrict__ a4l,
    const uint4* __restrict__ b4h, const uint4* __restrict__ b4l,
    int m0, int n0, int K, GemmFrag& F)
{
    __shared__ __align__(16) __nv_bfloat16 Ah[128][AS_];
    __shared__ __align__(16) __nv_bfloat16 Al[128][AS_];
    __shared__ __align__(16) __nv_bfloat16 Bh[32][BS_];
    __shared__ __align__(16) __nv_bfloat16 Bl[32][BS_];

    const int tid = threadIdx.x;
    const int lane = tid & 31;
    const int w = tid >> 5;
    const int wm = w >> 2, wn = w & 3;

    uint4* sAh = (uint4*)Ah; uint4* sAl = (uint4*)Al;
    uint4* sBh = (uint4*)Bh; uint4* sBl = (uint4*)Bl;

    const uint32_t Ah_b = (uint32_t)__cvta_generic_to_shared(Ah);
    const uint32_t Al_b = (uint32_t)__cvta_generic_to_shared(Al);
    const uint32_t Bh_b = (uint32_t)__cvta_generic_to_shared(Bh);
    const uint32_t Bl_b = (uint32_t)__cvta_generic_to_shared(Bl);

    const uint32_t a_off = (uint32_t)((wm * 64 + (lane & 15)) * (AS_ * 2) + (lane >> 4) * 16);
    const int l16 = lane & 15;
    const uint32_t b_off = (uint32_t)(((l16 & 7) + 8 * ((l16 >> 3) & 1)) * (BS_ * 2) + wn * 64);

#pragma unroll
    for (int mt = 0; mt < 4; mt++)
#pragma unroll
        for (int nt = 0; nt < 4; nt++)
#pragma unroll
            for (int i = 0; i < 4; i++) F.acc[mt][nt][i] = 0.f;

    for (int k0 = 0; k0 < K; k0 += 32) {
        // load A tile: 128 rows x 4 uint4
#pragma unroll
        for (int e = tid; e < 512; e += 256) {
            const int r = e >> 2, c = e & 3;
            const int gi = (m0 + r) * LDA_U4 + (k0 >> 3) + c;
            sAh[r * 5 + c] = a4h[gi];
            sAl[r * 5 + c] = a4l[gi];
        }
        // load B tile: 32 rows x 16 uint4
#pragma unroll
        for (int e = tid; e < 512; e += 256) {
            const int r = e >> 4, c = e & 15;
            const int gi = (k0 + r) * LDB_U4 + (n0 >> 3) + c;
            sBh[r * 17 + c] = b4h[gi];
            sBl[r * 17 + c] = b4l[gi];
        }
        __syncthreads();

#pragma unroll
        for (int ks = 0; ks < 2; ks++) {
            uint32_t ah[4][4], al[4][4], bh[4][2], bl[4][2];
#pragma unroll
            for (int mt = 0; mt < 4; mt++) {
                const uint32_t ao = a_off + (uint32_t)(mt * 16 * (AS_ * 2)) + ks * 32;
                LDSM4(ah[mt], Ah_b + ao);
                LDSM4(al[mt], Al_b + ao);
            }
#pragma unroll
            for (int nt = 0; nt < 4; nt++) {
                const uint32_t bo = b_off + (uint32_t)(ks * 16 * (BS_ * 2)) + nt * 16;
                LDSM2T(bh[nt], Bh_b + bo);
                LDSM2T(bl[nt], Bl_b + bo);
            }
#pragma unroll
            for (int mt = 0; mt < 4; mt++)
#pragma unroll
                for (int nt = 0; nt < 4; nt++) {
                    MMA16816(F.acc[mt][nt], ah[mt], bh[nt]);
                    MMA16816(F.acc[mt][nt], ah[mt], bl[nt]);
                    MMA16816(F.acc[mt][nt], al[mt], bh[nt]);
                }
        }
        __syncthreads();
    }
}

// =====================================================================
// Kernel 1: QKV GEMM on tensor cores; epilogue scatters split bf16
// q/k/v in [B,H,N,Dh] (Q pre-scaled).
// grid (C3/128=18, M/128=64), block 256.
// =====================================================================
__global__ __launch_bounds__(256) void qkv_mma_kernel()
{
    const int m0 = blockIdx.y * 128;
    const int n0 = blockIdx.x * 128;

    GemmFrag F;
    mma_gemm_tile<C_ / 8, C3_ / 8>((const uint4*)g_xh, (const uint4*)g_xl,
                                   (const uint4*)g_wqh, (const uint4*)g_wql,
                                   m0, n0, C_, F);

    const int tid = threadIdx.x;
    const int lane = tid & 31;
    const int w = tid >> 5;
    const int wm = w >> 2, wn = w & 3;

    const int b = m0 >> 12;
    const int s = n0 / C_;                       // 0=q,1=k,2=v (128 | 768)
    __nv_bfloat16* dh = (s == 0) ? g_qh : ((s == 1) ? g_kh : g_vh);
    __nv_bfloat16* dl = (s == 0) ? g_ql : ((s == 1) ? g_kl : g_vl);
    const float mul = (s == 0) ? QK_SCALE : 1.f;

#pragma unroll
    for (int mt = 0; mt < 4; mt++) {
        const int rbase = m0 + wm * 64 + mt * 16 + (lane >> 2);
#pragma unroll
        for (int nt = 0; nt < 4; nt++) {
            const int c0 = n0 + wn * 32 + nt * 8 + 2 * (lane & 3);
            const int rseg = c0 - s * C_;
            const int h = rseg / DH_;
            const int d = rseg - h * DH_;
#pragma unroll
            for (int pr = 0; pr < 2; pr++) {
                const int r = rbase + pr * 8;
                const int nidx = r & (N_ - 1);
                const size_t off = (((size_t)(b * H_ + h)) * N_ + nidx) * DH_ + d;
                float v0 = F.acc[mt][nt][2 * pr]     * mul;
                float v1 = F.acc[mt][nt][2 * pr + 1] * mul;
                __nv_bfloat162 h2, l2;
                split2(v0, v1, h2, l2);
                *(__nv_bfloat162*)(dh + off) = h2;
                *(__nv_bfloat162*)(dl + off) = l2;
            }
        }
    }
}

// =====================================================================
// Kernel 3: out projection on tensor cores + bias.
// grid (768/128=6, 64), block 256.
// =====================================================================
__global__ __launch_bounds__(256) void proj_mma_kernel(
    const float* __restrict__ bias, float* __restrict__ out)
{
    const int m0 = blockIdx.y * 128;
    const int n0 = blockIdx.x * 128;

    GemmFrag F;
    mma_gemm_tile<C_ / 8, C_ / 8>((const uint4*)g_ath, (const uint4*)g_atl,
                                  (const uint4*)g_wph, (const uint4*)g_wpl,
                                  m0, n0, C_, F);

    const int tid = threadIdx.x;
    const int lane = tid & 31;
    const int w = tid >> 5;
    const int wm = w >> 2, wn = w & 3;

#pragma unroll
    for (int mt = 0; mt < 4; mt++) {
        const int rbase = m0 + wm * 64 + mt * 16 + (lane >> 2);
#pragma unroll
        for (int nt = 0; nt < 4; nt++) {
            const int c0 = n0 + wn * 32 + nt * 8 + 2 * (lane & 3);
            const float b0 = bias[c0], b1 = bias[c0 + 1];
#pragma unroll
            for (int pr = 0; pr < 2; pr++) {
                const int r = rbase + pr * 8;
                float2 v = make_float2(F.acc[mt][nt][2 * pr] + b0,
                                       F.acc[mt][nt][2 * pr + 1] + b1);
                *(float2*)(out + (size_t)r * C_ + c0) = v;
            }
        }
    }
}

// =====================================================================
// Kernel 2: flash attention on tensor cores (unchanged core), epilogue
// now writes split bf16 att.
// =====================================================================
#define RS   104
#define RSB  (RS * 2)
#define SEG  (64 * RS)
#define ATT_SMEM_BYTES (6 * SEG * 2)   // 79872

__global__ __launch_bounds__(128) void attn_kernel()
{
    extern __shared__ __align__(16) char smem[];
    uint4* sQh4 = (uint4*)smem;
    uint4* sQl4 = (uint4*)(smem + 1 * SEG * 2);
    uint4* sKh4 = (uint4*)(smem + 2 * SEG * 2);
    uint4* sKl4 = (uint4*)(smem + 3 * SEG * 2);
    uint4* sVh4 = (uint4*)(smem + 4 * SEG * 2);
    uint4* sVl4 = (uint4*)(smem + 5 * SEG * 2);

    const int tid  = threadIdx.x;
    const int lane = tid & 31;
    const int w    = tid >> 5;
    const int bh   = blockIdx.y;
    const int q0   = blockIdx.x * 64;

    const uint32_t sb   = (uint32_t)__cvta_generic_to_shared(smem);
    const uint32_t Qh_b = sb;
    const uint32_t Ql_b = sb + 1 * SEG * 2;
    const uint32_t Kh_b = sb + 2 * SEG * 2;
    const uint32_t Kl_b = sb + 3 * SEG * 2;
    const uint32_t Vh_b = sb + 4 * SEG * 2;
    const uint32_t Vl_b = sb + 5 * SEG * 2;

    const uint4* q4h = (const uint4*)g_qh;
    const uint4* q4l = (const uint4*)g_ql;
    const size_t qrow0 = (size_t)bh * N_ + q0;
    for (int e = tid; e < 64 * 12; e += 128) {
        const int r = e / 12, c = e % 12;
        sQh4[r * 13 + c] = q4h[(qrow0 + r) * 12 + c];
        sQl4[r * 13 + c] = q4l[(qrow0 + r) * 12 + c];
    }

    const int mloc = w * 16;
    const uint32_t qa_off = (uint32_t)((mloc + (lane & 7) + 8 * ((lane >> 3) & 1)) * RSB
                                       + (lane >> 4) * 16);
    const int l16 = lane & 15;
    const uint32_t kb_off = (uint32_t)((l16 & 7) * RSB + ((l16 >> 3) & 1) * 16);
    const uint32_t vb_off = (uint32_t)(((l16 & 7) + 8 * ((l16 >> 3) & 1)) * RSB);

    float oc[12][4];
#pragma unroll
    for (int nt = 0; nt < 12; nt++)
#pragma unroll
        for (int i = 0; i < 4; i++) oc[nt][i] = 0.f;
    float mprev[2] = {-1e30f, -1e30f};
    float lsum[2]  = {0.f, 0.f};

    const uint4* k4h = (const uint4*)g_kh;
    const uint4* k4l = (const uint4*)g_kl;
    const uint4* v4h = (const uint4*)g_vh;
    const uint4* v4l = (const uint4*)g_vl;

    for (int t0 = 0; t0 < N_; t0 += 64) {
        __syncthreads();
        const size_t krow0 = (size_t)bh * N_ + t0;
        for (int e = tid; e < 64 * 12; e += 128) {
            const int r = e / 12, c = e % 12;
            const size_t gi = (krow0 + r) * 12 + c;
            const int si = r * 13 + c;
            sKh4[si] = k4h[gi];
            sKl4[si] = k4l[gi];
            sVh4[si] = v4h[gi];
            sVl4[si] = v4l[gi];
        }
        __syncthreads();

        float sc[8][4];
#pragma unroll
        for (int nt = 0; nt < 8; nt++)
#pragma unroll
            for (int i = 0; i < 4; i++) sc[nt][i] = 0.f;

#pragma unroll
        for (int kc = 0; kc < 6; kc++) {
            uint32_t qh[4], ql[4];
            LDSM4(qh, Qh_b + qa_off + kc * 32);
            LDSM4(ql, Ql_b + qa_off + kc * 32);
#pragma unroll
            for (int nt = 0; nt < 8; nt++) {
                uint32_t kh[2], kl[2];
                const uint32_t off = kb_off + (uint32_t)(nt * 8 * RSB) + kc * 32;
                LDSM2(kh, Kh_b + off);
                LDSM2(kl, Kl_b + off);
                MMA16816(sc[nt], qh, kh);
                MMA16816(sc[nt], qh, kl);
                MMA16816(sc[nt], ql, kh);
            }
        }

        float alpha[2];
#pragma unroll
        for (int rh = 0; rh < 2; rh++) {
            float mt = -1e30f;
#pragma unroll
            for (int nt = 0; nt < 8; nt++)
                mt = fmaxf(mt, fmaxf(sc[nt][2 * rh], sc[nt][2 * rh + 1]));
            mt = fmaxf(mt, __shfl_xor_sync(0xffffffffu, mt, 1));
            mt = fmaxf(mt, __shfl_xor_sync(0xffffffffu, mt, 2));
            const float mnew = fmaxf(mprev[rh], mt);
            alpha[rh] = __expf(mprev[rh] - mnew);
            float ls = 0.f;
#pragma unroll
            for (int nt = 0; nt < 8; nt++) {
                const float e0 = __expf(sc[nt][2 * rh]     - mnew);
                const float e1 = __expf(sc[nt][2 * rh + 1] - mnew);
                sc[nt][2 * rh] = e0; sc[nt][2 * rh + 1] = e1;
                ls += e0 + e1;
            }
            ls += __shfl_xor_sync(0xffffffffu, ls, 1);
            ls += __shfl_xor_sync(0xffffffffu, ls, 2);
            lsum[rh] = lsum[rh] * alpha[rh] + ls;
            mprev[rh] = mnew;
        }
#pragma unroll
        for (int nt = 0; nt < 12; nt++) {
            oc[nt][0] *= alpha[0]; oc[nt][1] *= alpha[0];
            oc[nt][2] *= alpha[1]; oc[nt][3] *= alpha[1];
        }

#pragma unroll
        for (int kc = 0; kc < 4; kc++) {
            const int ta = 2 * kc, tb = 2 * kc + 1;
            uint32_t ph[4], pl[4];
            ph[0] = packpair(sc[ta][0], sc[ta][1]);
            ph[1] = packpair(sc[ta][2], sc[ta][3]);
            ph[2] = packpair(sc[tb][0], sc[tb][1]);
            ph[3] = packpair(sc[tb][2], sc[tb][3]);
            pl[0] = packpair(bf_res(sc[ta][0]), bf_res(sc[ta][1]));
            pl[1] = packpair(bf_res(sc[ta][2]), bf_res(sc[ta][3]));
            pl[2] = packpair(bf_res(sc[tb][0]), bf_res(sc[tb][1]));
            pl[3] = packpair(bf_res(sc[tb][2]), bf_res(sc[tb][3]));
#pragma unroll
            for (int nt = 0; nt < 12; nt++) {
                uint32_t vh[2], vl[2];
                const uint32_t off = vb_off + (uint32_t)(kc * 16 * RSB) + nt * 16;
                LDSM2T(vh, Vh_b + off);
                LDSM2T(vl, Vl_b + off);
                MMA16816(oc[nt], ph, vh);
                MMA16816(oc[nt], ph, vl);
                MMA16816(oc[nt], pl, vh);
            }
        }
    }

    // epilogue: normalize, split to bf16 hi/lo, write [B,N,C]
    const int b = bh >> 3, h = bh & 7;
    const int r0 = q0 + mloc + (lane >> 2);
    const float inv0 = 1.f / lsum[0];
    const float inv1 = 1.f / lsum[1];
    const size_t base0 = ((size_t)(b * N_ + r0)) * C_ + h * DH_ + 2 * (lane & 3);
    const size_t base1 = base0 + (size_t)8 * C_;
#pragma unroll
    for (int nt = 0; nt < 12; nt++) {
        __nv_bfloat162 h2, l2;
        split2(oc[nt][0] * inv0, oc[nt][1] * inv0, h2, l2);
        *(__nv_bfloat162*)(g_ath + base0 + nt * 8) = h2;
        *(__nv_bfloat162*)(g_atl + base0 + nt * 8) = l2;
        split2(oc[nt][2] * inv1, oc[nt][3] * inv1, h2, l2);
        *(__nv_bfloat162*)(g_ath + base1 + nt * 8) = h2;
        *(__nv_bfloat162*)(g_atl + base1 + nt * 8) = l2;
    }
}

// =====================================================================
extern "C" void kernel_launch(void* const* d_in, const int* in_sizes, int n_in,
                              void* d_out, int out_size)
{
    const float* x     = (const float*)d_in[0];
    const float* wqkv  = (const float*)d_in[1];
    const float* wproj = (const float*)d_in[2];
    const float* bproj = (const float*)d_in[3];
    float* out = (float*)d_out;

    (void)in_sizes; (void)n_in; (void)out_size;

    __nv_bfloat16 *xh, *xl, *wqh, *wql, *wph, *wpl;
    cudaGetSymbolAddress((void**)&xh,  g_xh);
    cudaGetSymbolAddress((void**)&xl,  g_xl);
    cudaGetSymbolAddress((void**)&wqh, g_wqh);
    cudaGetSymbolAddress((void**)&wql, g_wql);
    cudaGetSymbolAddress((void**)&wph, g_wph);
    cudaGetSymbolAddress((void**)&wpl, g_wpl);

    // 0. split inputs to bf16 hi/lo
    {
        int n4 = M_ * C_ / 4;
        split_kernel<<<(n4 + 255) / 256, 256>>>(x, xh, xl, n4);
        n4 = C_ * C3_ / 4;
        split_kernel<<<(n4 + 255) / 256, 256>>>(wqkv, wqh, wql, n4);
        n4 = C_ * C_ / 4;
        split_kernel<<<(n4 + 255) / 256, 256>>>(wproj, wph, wpl, n4);
    }

    // 1. QKV projection (tensor cores) + split scatter
    {
        dim3 grid(C3_ / 128, M_ / 128);   // (18, 64)
        qkv_mma_kernel<<<grid, 256>>>();
    }

    // 2. flash attention (tensor cores)
    {
        cudaFuncSetAttribute(attn_kernel,
                             cudaFuncAttributeMaxDynamicSharedMemorySize, ATT_SMEM_BYTES);
        dim3 grid(N_ / 64, B_ * H_);      // (64, 16)
        attn_kernel<<<grid, 128, ATT_SMEM_BYTES>>>();
    }

    // 3. output projection (tensor cores) + bias
    {
        dim3 grid(C_ / 128, M_ / 128);    // (6, 64)
        proj_mma_kernel<<<grid, 256>>>(bproj, out);
    }
}

// round 7
// speedup vs baseline: 3.3463x; 1.3493x over previous
#include <cuda_runtime.h>
#include <cuda_bf16.h>
#include <math.h>
#include <stdint.h>

// Problem dims (fixed by reference)
#define B_   2
#define N_   4096
#define C_   768
#define H_   8
#define DH_  96
#define C3_  2304
#define M_   (B_ * N_)          // 8192 rows

#define QK_SCALE 0.10206207261596577f   // 96^-0.5

// ---------------- device-global scratch ----------------
__device__ __align__(16) __nv_bfloat16 g_xh[M_ * C_];
__device__ __align__(16) __nv_bfloat16 g_xl[M_ * C_];
__device__ __align__(16) __nv_bfloat16 g_wqh[C_ * C3_];
__device__ __align__(16) __nv_bfloat16 g_wql[C_ * C3_];
__device__ __align__(16) __nv_bfloat16 g_wph[C_ * C_];
__device__ __align__(16) __nv_bfloat16 g_wpl[C_ * C_];
__device__ __align__(16) __nv_bfloat16 g_qh[B_ * H_ * N_ * DH_];
__device__ __align__(16) __nv_bfloat16 g_ql[B_ * H_ * N_ * DH_];
__device__ __align__(16) __nv_bfloat16 g_kh[B_ * H_ * N_ * DH_];
__device__ __align__(16) __nv_bfloat16 g_kl[B_ * H_ * N_ * DH_];
__device__ __align__(16) __nv_bfloat16 g_vh[B_ * H_ * N_ * DH_];
__device__ __align__(16) __nv_bfloat16 g_vl[B_ * H_ * N_ * DH_];
__device__ __align__(16) __nv_bfloat16 g_ath[B_ * N_ * C_];
__device__ __align__(16) __nv_bfloat16 g_atl[B_ * N_ * C_];

// ---------------- asm helpers ----------------
#define LDSM4(d, a) asm volatile( \
    "ldmatrix.sync.aligned.m8n8.x4.shared.b16 {%0,%1,%2,%3}, [%4];" \
    : "=r"((d)[0]), "=r"((d)[1]), "=r"((d)[2]), "=r"((d)[3]) : "r"(a))
#define LDSM4T(d, a) asm volatile( \
    "ldmatrix.sync.aligned.m8n8.x4.trans.shared.b16 {%0,%1,%2,%3}, [%4];" \
    : "=r"((d)[0]), "=r"((d)[1]), "=r"((d)[2]), "=r"((d)[3]) : "r"(a))
#define MMA16816(c, a, b) asm volatile( \
    "mma.sync.aligned.m16n8k16.row.col.f32.bf16.bf16.f32 " \
    "{%0,%1,%2,%3}, {%4,%5,%6,%7}, {%8,%9}, {%0,%1,%2,%3};" \
    : "+f"((c)[0]), "+f"((c)[1]), "+f"((c)[2]), "+f"((c)[3]) \
    : "r"((a)[0]), "r"((a)[1]), "r"((a)[2]), "r"((a)[3]), "r"((b)[0]), "r"((b)[1]))

__device__ __forceinline__ void cp16(uint32_t dst, const void* src) {
    asm volatile("cp.async.cg.shared.global [%0], [%1], 16;" :: "r"(dst), "l"(src));
}
#define CP_COMMIT() asm volatile("cp.async.commit_group;")
#define CP_WAIT(n)  asm volatile("cp.async.wait_group %0;" :: "n"(n))

__device__ __forceinline__ uint32_t packpair(float lo, float hi) {
    __nv_bfloat162 t = __floats2bfloat162_rn(lo, hi);
    return *(uint32_t*)&t;
}
__device__ __forceinline__ float bf_res(float x) {
    return x - __bfloat162float(__float2bfloat16(x));
}
__device__ __forceinline__ void split2(float v0, float v1,
                                       __nv_bfloat162& h2, __nv_bfloat162& l2) {
    __nv_bfloat16 h0 = __float2bfloat16(v0);
    __nv_bfloat16 h1 = __float2bfloat16(v1);
    __nv_bfloat16 l0 = __float2bfloat16(v0 - __bfloat162float(h0));
    __nv_bfloat16 l1 = __float2bfloat16(v1 - __bfloat162float(h1));
    h2 = __nv_bfloat162(h0, h1);
    l2 = __nv_bfloat162(l0, l1);
}

// =====================================================================
// split kernel: fp32 -> bf16 hi/lo
// =====================================================================
__global__ void split_kernel(const float* __restrict__ src,
                             __nv_bfloat16* __restrict__ h,
                             __nv_bfloat16* __restrict__ l, int n4)
{
    int i = blockIdx.x * blockDim.x + threadIdx.x;
    if (i >= n4) return;
    float4 v = ((const float4*)src)[i];
    __nv_bfloat162 h0, l0, h1, l1;
    split2(v.x, v.y, h0, l0);
    split2(v.z, v.w, h1, l1);
    ((__nv_bfloat162*)h)[2 * i]     = h0;
    ((__nv_bfloat162*)h)[2 * i + 1] = h1;
    ((__nv_bfloat162*)l)[2 * i]     = l0;
    ((__nv_bfloat162*)l)[2 * i + 1] = l1;
}

// =====================================================================
// MMA GEMM body: 128x128 tile, BK=32, 8 warps, double-buffered cp.async.
// Dynamic smem layout (uint4 units):
//   Ah[2][A_SEG4] | Al[2][A_SEG4] | Bh[2][B_SEG4] | Bl[2][B_SEG4]
// =====================================================================
#define ASB  80                 // A smem row stride bytes (40 bf16)
#define BSB  272                // B smem row stride bytes (136 bf16)
#define A_SEG4 (128 * 5)        // uint4 per A stage (640)
#define B_SEG4 (32 * 17)        // uint4 per B stage (544)
#define GEMM_SMEM_BYTES ((4 * A_SEG4 + 4 * B_SEG4) * 16)   // 75776

struct GemmFrag { float acc[4][4][4]; };

template<int LDA_U4, int LDB_U4>
__device__ __forceinline__ void mma_gemm_tile(
    uint32_t sb,
    const uint4* __restrict__ a4h, const uint4* __restrict__ a4l,
    const uint4* __restrict__ b4h, const uint4* __restrict__ b4l,
    int m0, int n0, int K, GemmFrag& F)
{
    const int tid = threadIdx.x;
    const int lane = tid & 31;
    const int w = tid >> 5;
    const int wm = w >> 2, wn = w & 3;

    const uint32_t ASEGB = A_SEG4 * 16;
    const uint32_t BSEGB = B_SEG4 * 16;
    const uint32_t Ah_b = sb;
    const uint32_t Al_b = sb + 2 * ASEGB;
    const uint32_t Bh_b = sb + 4 * ASEGB;
    const uint32_t Bl_b = sb + 4 * ASEGB + 2 * BSEGB;

    const uint32_t a_off = (uint32_t)((wm * 64 + (lane & 15)) * ASB + (lane >> 4) * 16);
    const uint32_t b_off = (uint32_t)(((lane & 7) + 8 * ((lane >> 3) & 1)) * BSB
                                      + (lane >> 4) * 16 + wn * 64);

#pragma unroll
    for (int mt = 0; mt < 4; mt++)
#pragma unroll
        for (int nt = 0; nt < 4; nt++)
#pragma unroll
            for (int i = 0; i < 4; i++) F.acc[mt][nt][i] = 0.f;

    const int KT = K / 32;

    // prologue: stage 0
    {
#pragma unroll
        for (int e = tid; e < 512; e += 256) {
            const int r = e >> 2, c = e & 3;
            const int gi = (m0 + r) * LDA_U4 + c;
            const uint32_t so = (uint32_t)(r * 5 + c) * 16;
            cp16(Ah_b + so, a4h + gi);
            cp16(Al_b + so, a4l + gi);
        }
#pragma unroll
        for (int e = tid; e < 512; e += 256) {
            const int r = e >> 4, c = e & 15;
            const int gi = r * LDB_U4 + (n0 >> 3) + c;
            const uint32_t so = (uint32_t)(r * 17 + c) * 16;
            cp16(Bh_b + so, b4h + gi);
            cp16(Bl_b + so, b4l + gi);
        }
        CP_COMMIT();
    }

    for (int kt = 0; kt < KT; kt++) {
        const int stage = kt & 1;
        if (kt + 1 < KT) {
            const int ns = stage ^ 1;
            const int k0 = (kt + 1) * 32;
#pragma unroll
            for (int e = tid; e < 512; e += 256) {
                const int r = e >> 2, c = e & 3;
                const int gi = (m0 + r) * LDA_U4 + (k0 >> 3) + c;
                const uint32_t so = (uint32_t)ns * ASEGB + (uint32_t)(r * 5 + c) * 16;
                cp16(Ah_b + so, a4h + gi);
                cp16(Al_b + so, a4l + gi);
            }
#pragma unroll
            for (int e = tid; e < 512; e += 256) {
                const int r = e >> 4, c = e & 15;
                const int gi = (k0 + r) * LDB_U4 + (n0 >> 3) + c;
                const uint32_t so = (uint32_t)ns * BSEGB + (uint32_t)(r * 17 + c) * 16;
                cp16(Bh_b + so, b4h + gi);
                cp16(Bl_b + so, b4l + gi);
            }
            CP_COMMIT();
            CP_WAIT(1);
        } else {
            CP_WAIT(0);
        }
        __syncthreads();

        const uint32_t AhS = Ah_b + (uint32_t)stage * ASEGB;
        const uint32_t AlS = Al_b + (uint32_t)stage * ASEGB;
        const uint32_t BhS = Bh_b + (uint32_t)stage * BSEGB;
        const uint32_t BlS = Bl_b + (uint32_t)stage * BSEGB;

#pragma unroll
        for (int ks = 0; ks < 2; ks++) {
            uint32_t ah[4][4], al[4][4], bh4[2][4], bl4[2][4];
#pragma unroll
            for (int mt = 0; mt < 4; mt++) {
                const uint32_t ao = a_off + (uint32_t)(mt * 16 * ASB) + ks * 32;
                LDSM4(ah[mt], AhS + ao);
                LDSM4(al[mt], AlS + ao);
            }
#pragma unroll
            for (int np = 0; np < 2; np++) {
                const uint32_t bo = b_off + (uint32_t)(ks * 16 * BSB) + np * 32;
                LDSM4T(bh4[np], BhS + bo);
                LDSM4T(bl4[np], BlS + bo);
            }
#pragma unroll
            for (int mt = 0; mt < 4; mt++)
#pragma unroll
                for (int np = 0; np < 2; np++) {
                    MMA16816(F.acc[mt][2 * np],     ah[mt], bh4[np]);
                    MMA16816(F.acc[mt][2 * np],     ah[mt], bl4[np]);
                    MMA16816(F.acc[mt][2 * np],     al[mt], bh4[np]);
                    MMA16816(F.acc[mt][2 * np + 1], ah[mt], bh4[np] + 2);
                    MMA16816(F.acc[mt][2 * np + 1], ah[mt], bl4[np] + 2);
                    MMA16816(F.acc[mt][2 * np + 1], al[mt], bh4[np] + 2);
                }
        }
        __syncthreads();
    }
}

// =====================================================================
// Kernel 1: QKV GEMM (tensor cores) + split scatter
// =====================================================================
__global__ __launch_bounds__(256) void qkv_mma_kernel()
{
    extern __shared__ __align__(16) char gsm[];
    const uint32_t sb = (uint32_t)__cvta_generic_to_shared(gsm);

    const int m0 = blockIdx.y * 128;
    const int n0 = blockIdx.x * 128;

    GemmFrag F;
    mma_gemm_tile<C_ / 8, C3_ / 8>(sb, (const uint4*)g_xh, (const uint4*)g_xl,
                                   (const uint4*)g_wqh, (const uint4*)g_wql,
                                   m0, n0, C_, F);

    const int tid = threadIdx.x;
    const int lane = tid & 31;
    const int w = tid >> 5;
    const int wm = w >> 2, wn = w & 3;

    const int b = m0 >> 12;
    const int s = n0 / C_;
    __nv_bfloat16* dh = (s == 0) ? g_qh : ((s == 1) ? g_kh : g_vh);
    __nv_bfloat16* dl = (s == 0) ? g_ql : ((s == 1) ? g_kl : g_vl);
    const float mul = (s == 0) ? QK_SCALE : 1.f;

#pragma unroll
    for (int mt = 0; mt < 4; mt++) {
        const int rbase = m0 + wm * 64 + mt * 16 + (lane >> 2);
#pragma unroll
        for (int nt = 0; nt < 4; nt++) {
            const int c0 = n0 + wn * 32 + nt * 8 + 2 * (lane & 3);
            const int rseg = c0 - s * C_;
            const int h = rseg / DH_;
            const int d = rseg - h * DH_;
#pragma unroll
            for (int pr = 0; pr < 2; pr++) {
                const int r = rbase + pr * 8;
                const int nidx = r & (N_ - 1);
                const size_t off = (((size_t)(b * H_ + h)) * N_ + nidx) * DH_ + d;
                float v0 = F.acc[mt][nt][2 * pr]     * mul;
                float v1 = F.acc[mt][nt][2 * pr + 1] * mul;
                __nv_bfloat162 h2, l2;
                split2(v0, v1, h2, l2);
                *(__nv_bfloat162*)(dh + off) = h2;
                *(__nv_bfloat162*)(dl + off) = l2;
            }
        }
    }
}

// =====================================================================
// Kernel 3: out projection (tensor cores) + bias
// =====================================================================
__global__ __launch_bounds__(256) void proj_mma_kernel(
    const float* __restrict__ bias, float* __restrict__ out)
{
    extern __shared__ __align__(16) char gsm[];
    const uint32_t sb = (uint32_t)__cvta_generic_to_shared(gsm);

    const int m0 = blockIdx.y * 128;
    const int n0 = blockIdx.x * 128;

    GemmFrag F;
    mma_gemm_tile<C_ / 8, C_ / 8>(sb, (const uint4*)g_ath, (const uint4*)g_atl,
                                  (const uint4*)g_wph, (const uint4*)g_wpl,
                                  m0, n0, C_, F);

    const int tid = threadIdx.x;
    const int lane = tid & 31;
    const int w = tid >> 5;
    const int wm = w >> 2, wn = w & 3;

#pragma unroll
    for (int mt = 0; mt < 4; mt++) {
        const int rbase = m0 + wm * 64 + mt * 16 + (lane >> 2);
#pragma unroll
        for (int nt = 0; nt < 4; nt++) {
            const int c0 = n0 + wn * 32 + nt * 8 + 2 * (lane & 3);
            const float b0 = bias[c0], b1 = bias[c0 + 1];
#pragma unroll
            for (int pr = 0; pr < 2; pr++) {
                const int r = rbase + pr * 8;
                float2 v = make_float2(F.acc[mt][nt][2 * pr] + b0,
                                       F.acc[mt][nt][2 * pr + 1] + b1);
                *(float2*)(out + (size_t)r * C_ + c0) = v;
            }
        }
    }
}

// =====================================================================
// Kernel 2: flash attention. BQ=128, 8 warps, double-buffered K/V via
// cp.async; all ldmatrix x4.
// =====================================================================
#define RSB  208                 // row stride bytes (104 bf16 = 13 uint4)
#define QSEG4  (128 * 13)        // Q array size, uint4
#define KSEG4  (64 * 13)         // per-stage KV array size, uint4
#define KSEGB  (KSEG4 * 16)
#define ATT_SMEM_BYTES ((2 * QSEG4 + 8 * KSEG4) * 16)   // 159744

__global__ __launch_bounds__(256) void attn_kernel()
{
    extern __shared__ __align__(16) uint4 sm4[];

    const int tid  = threadIdx.x;
    const int lane = tid & 31;
    const int w    = tid >> 5;
    const int bh   = blockIdx.y;
    const int q0   = blockIdx.x * 128;

    const uint32_t sb   = (uint32_t)__cvta_generic_to_shared(sm4);
    const uint32_t Qh_b = sb;
    const uint32_t Ql_b = sb + QSEG4 * 16;
    const uint32_t Kh_b = sb + 2 * QSEG4 * 16;
    const uint32_t Kl_b = Kh_b + 2 * KSEGB;
    const uint32_t Vh_b = Kl_b + 2 * KSEGB;
    const uint32_t Vl_b = Vh_b + 2 * KSEGB;

    const uint4* q4h = (const uint4*)g_qh;
    const uint4* q4l = (const uint4*)g_ql;
    const uint4* k4h = (const uint4*)g_kh;
    const uint4* k4l = (const uint4*)g_kl;
    const uint4* v4h = (const uint4*)g_vh;
    const uint4* v4l = (const uint4*)g_vl;
    const size_t qrow0 = (size_t)bh * N_ + q0;
    const size_t krow0 = (size_t)bh * N_;

    // prologue: Q (all 128 rows) + KV stage 0, one commit group
    for (int e = tid; e < 128 * 12; e += 256) {
        const int r = e / 12, c = e % 12;
        const uint32_t so = (uint32_t)(r * 13 + c) * 16;
        cp16(Qh_b + so, q4h + (qrow0 + r) * 12 + c);
        cp16(Ql_b + so, q4l + (qrow0 + r) * 12 + c);
    }
    for (int e = tid; e < 64 * 12; e += 256) {
        const int r = e / 12, c = e % 12;
        const size_t gi = (krow0 + r) * 12 + c;
        const uint32_t so = (uint32_t)(r * 13 + c) * 16;
        cp16(Kh_b + so, k4h + gi);
        cp16(Kl_b + so, k4l + gi);
        cp16(Vh_b + so, v4h + gi);
        cp16(Vl_b + so, v4l + gi);
    }
    CP_COMMIT();

    // fragment offsets
    const int mloc = w * 16;
    const uint32_t qa_off = (uint32_t)((mloc + (lane & 7) + 8 * ((lane >> 3) & 1)) * RSB
                                       + (lane >> 4) * 16);
    const uint32_t koff = (uint32_t)(((lane & 7) + 8 * (lane >> 4)) * RSB
                                     + ((lane >> 3) & 1) * 16);
    const uint32_t voff = (uint32_t)(((lane & 7) + 8 * ((lane >> 3) & 1)) * RSB
                                     + (lane >> 4) * 16);

    float oc[12][4];
#pragma unroll
    for (int nt = 0; nt < 12; nt++)
#pragma unroll
        for (int i = 0; i < 4; i++) oc[nt][i] = 0.f;
    float mprev[2] = {-1e30f, -1e30f};
    float lsum[2]  = {0.f, 0.f};

    for (int t = 0; t < N_ / 64; t++) {
        const int stage = t & 1;
        if (t + 1 < N_ / 64) {
            const int ns = stage ^ 1;
            const size_t kr = krow0 + (size_t)(t + 1) * 64;
            const uint32_t sofs = (uint32_t)ns * KSEGB;
            for (int e = tid; e < 64 * 12; e += 256) {
                const int r = e / 12, c = e % 12;
                const size_t gi = (kr + r) * 12 + c;
                const uint32_t so = sofs + (uint32_t)(r * 13 + c) * 16;
                cp16(Kh_b + so, k4h + gi);
                cp16(Kl_b + so, k4l + gi);
                cp16(Vh_b + so, v4h + gi);
                cp16(Vl_b + so, v4l + gi);
            }
            CP_COMMIT();
            CP_WAIT(1);
        } else {
            CP_WAIT(0);
        }
        __syncthreads();

        const uint32_t KhS = Kh_b + (uint32_t)stage * KSEGB;
        const uint32_t KlS = Kl_b + (uint32_t)stage * KSEGB;
        const uint32_t VhS = Vh_b + (uint32_t)stage * KSEGB;
        const uint32_t VlS = Vl_b + (uint32_t)stage * KSEGB;

        // ---- S = Q K^T ----
        float sc[8][4];
#pragma unroll
        for (int nt = 0; nt < 8; nt++)
#pragma unroll
            for (int i = 0; i < 4; i++) sc[nt][i] = 0.f;

#pragma unroll
        for (int kc = 0; kc < 6; kc++) {
            uint32_t qh[4], ql[4];
            LDSM4(qh, Qh_b + qa_off + kc * 32);
            LDSM4(ql, Ql_b + qa_off + kc * 32);
#pragma unroll
            for (int np = 0; np < 4; np++) {
                uint32_t kh4[4], kl4[4];
                const uint32_t o = koff + (uint32_t)(np * 16 * RSB) + kc * 32;
                LDSM4(kh4, KhS + o);
                LDSM4(kl4, KlS + o);
                MMA16816(sc[2 * np],     qh, kh4);
                MMA16816(sc[2 * np],     qh, kl4);
                MMA16816(sc[2 * np],     ql, kh4);
                MMA16816(sc[2 * np + 1], qh, kh4 + 2);
                MMA16816(sc[2 * np + 1], qh, kl4 + 2);
                MMA16816(sc[2 * np + 1], ql, kh4 + 2);
            }
        }

        // ---- online softmax ----
        float alpha[2];
#pragma unroll
        for (int rh = 0; rh < 2; rh++) {
            float mt = -1e30f;
#pragma unroll
            for (int nt = 0; nt < 8; nt++)
                mt = fmaxf(mt, fmaxf(sc[nt][2 * rh], sc[nt][2 * rh + 1]));
            mt = fmaxf(mt, __shfl_xor_sync(0xffffffffu, mt, 1));
            mt = fmaxf(mt, __shfl_xor_sync(0xffffffffu, mt, 2));
            const float mnew = fmaxf(mprev[rh], mt);
            alpha[rh] = __expf(mprev[rh] - mnew);
            float ls = 0.f;
#pragma unroll
            for (int nt = 0; nt < 8; nt++) {
                const float e0 = __expf(sc[nt][2 * rh]     - mnew);
                const float e1 = __expf(sc[nt][2 * rh + 1] - mnew);
                sc[nt][2 * rh] = e0; sc[nt][2 * rh + 1] = e1;
                ls += e0 + e1;
            }
            ls += __shfl_xor_sync(0xffffffffu, ls, 1);
            ls += __shfl_xor_sync(0xffffffffu, ls, 2);
            lsum[rh] = lsum[rh] * alpha[rh] + ls;
            mprev[rh] = mnew;
        }
#pragma unroll
        for (int nt = 0; nt < 12; nt++) {
            oc[nt][0] *= alpha[0]; oc[nt][1] *= alpha[0];
            oc[nt][2] *= alpha[1]; oc[nt][3] *= alpha[1];
        }

        // ---- O += P V ----
#pragma unroll
        for (int kc = 0; kc < 4; kc++) {
            const int ta = 2 * kc, tb = 2 * kc + 1;
            uint32_t ph[4], pl[4];
            ph[0] = packpair(sc[ta][0], sc[ta][1]);
            ph[1] = packpair(sc[ta][2], sc[ta][3]);
            ph[2] = packpair(sc[tb][0], sc[tb][1]);
            ph[3] = packpair(sc[tb][2], sc[tb][3]);
            pl[0] = packpair(bf_res(sc[ta][0]), bf_res(sc[ta][1]));
            pl[1] = packpair(bf_res(sc[ta][2]), bf_res(sc[ta][3]));
            pl[2] = packpair(bf_res(sc[tb][0]), bf_res(sc[tb][1]));
            pl[3] = packpair(bf_res(sc[tb][2]), bf_res(sc[tb][3]));
#pragma unroll
            for (int np = 0; np < 6; np++) {
                uint32_t vh4[4], vl4[4];
                const uint32_t o = voff + (uint32_t)(kc * 16 * RSB) + np * 32;
                LDSM4T(vh4, VhS + o);
                LDSM4T(vl4, VlS + o);
                MMA16816(oc[2 * np],     ph, vh4);
                MMA16816(oc[2 * np],     ph, vl4);
                MMA16816(oc[2 * np],     pl, vh4);
                MMA16816(oc[2 * np + 1], ph, vh4 + 2);
                MMA16816(oc[2 * np + 1], ph, vl4 + 2);
                MMA16816(oc[2 * np + 1], pl, vh4 + 2);
            }
        }
        __syncthreads();
    }

    // ---- epilogue: normalize, split bf16, write [B,N,C] ----
    const int b = bh >> 3, h = bh & 7;
    const int r0 = q0 + mloc + (lane >> 2);
    const float inv0 = 1.f / lsum[0];
    const float inv1 = 1.f / lsum[1];
    const size_t base0 = ((size_t)(b * N_ + r0)) * C_ + h * DH_ + 2 * (lane & 3);
    const size_t base1 = base0 + (size_t)8 * C_;
#pragma unroll
    for (int nt = 0; nt < 12; nt++) {
        __nv_bfloat162 h2, l2;
        split2(oc[nt][0] * inv0, oc[nt][1] * inv0, h2, l2);
        *(__nv_bfloat162*)(g_ath + base0 + nt * 8) = h2;
        *(__nv_bfloat162*)(g_atl + base0 + nt * 8) = l2;
        split2(oc[nt][2] * inv1, oc[nt][3] * inv1, h2, l2);
        *(__nv_bfloat162*)(g_ath + base1 + nt * 8) = h2;
        *(__nv_bfloat162*)(g_atl + base1 + nt * 8) = l2;
    }
}

// =====================================================================
extern "C" void kernel_launch(void* const* d_in, const int* in_sizes, int n_in,
                              void* d_out, int out_size)
{
    const float* x     = (const float*)d_in[0];
    const float* wqkv  = (const float*)d_in[1];
    const float* wproj = (const float*)d_in[2];
    const float* bproj = (const float*)d_in[3];
    float* out = (float*)d_out;

    (void)in_sizes; (void)n_in; (void)out_size;

    __nv_bfloat16 *xh, *xl, *wqh, *wql, *wph, *wpl;
    cudaGetSymbolAddress((void**)&xh,  g_xh);
    cudaGetSymbolAddress((void**)&xl,  g_xl);
    cudaGetSymbolAddress((void**)&wqh, g_wqh);
    cudaGetSymbolAddress((void**)&wql, g_wql);
    cudaGetSymbolAddress((void**)&wph, g_wph);
    cudaGetSymbolAddress((void**)&wpl, g_wpl);

    // 0. split inputs to bf16 hi/lo
    {
        int n4 = M_ * C_ / 4;
        split_kernel<<<(n4 + 255) / 256, 256>>>(x, xh, xl, n4);
        n4 = C_ * C3_ / 4;
        split_kernel<<<(n4 + 255) / 256, 256>>>(wqkv, wqh, wql, n4);
        n4 = C_ * C_ / 4;
        split_kernel<<<(n4 + 255) / 256, 256>>>(wproj, wph, wpl, n4);
    }

    // 1. QKV projection + split scatter
    {
        cudaFuncSetAttribute(qkv_mma_kernel,
                             cudaFuncAttributeMaxDynamicSharedMemorySize, GEMM_SMEM_BYTES);
        dim3 grid(C3_ / 128, M_ / 128);   // (18, 64)
        qkv_mma_kernel<<<grid, 256, GEMM_SMEM_BYTES>>>();
    }

    // 2. flash attention
    {
        cudaFuncSetAttribute(attn_kernel,
                             cudaFuncAttributeMaxDynamicSharedMemorySize, ATT_SMEM_BYTES);
        dim3 grid(N_ / 128, B_ * H_);     // (32, 16)
        attn_kernel<<<grid, 256, ATT_SMEM_BYTES>>>();
    }

    // 3. output projection + bias
    {
        cudaFuncSetAttribute(proj_mma_kernel,
                             cudaFuncAttributeMaxDynamicSharedMemorySize, GEMM_SMEM_BYTES);
        dim3 grid(C_ / 128, M_ / 128);    // (6, 64)
        proj_mma_kernel<<<grid, 256, GEMM_SMEM_BYTES>>>(bproj, out);
    }
}